// round 8
// baseline (speedup 1.0000x reference)
#include <cuda_runtime.h>
#include <math.h>
#include <stdint.h>

#define B  8
#define C  64
#define Hc 256
#define Wc 256
#define CR 128
#define HR 128
#define WR 128

__device__ float g_scores[B * CR];
__device__ int   g_idx[B * C];

// ---------------------------------------------------------------------------
// mbarrier / bulk-async helpers
// ---------------------------------------------------------------------------
__device__ __forceinline__ uint32_t smem_u32(const void* p) {
    uint32_t a;
    asm("{ .reg .u64 t; cvta.to.shared.u64 t, %1; cvt.u32.u64 %0, t; }"
        : "=r"(a) : "l"(p));
    return a;
}
__device__ __forceinline__ void mbar_init(uint32_t a, uint32_t cnt) {
    asm volatile("mbarrier.init.shared.b64 [%0], %1;" :: "r"(a), "r"(cnt) : "memory");
}
__device__ __forceinline__ void mbar_expect(uint32_t a, uint32_t bytes) {
    asm volatile("mbarrier.arrive.expect_tx.shared.b64 _, [%0], %1;"
                 :: "r"(a), "r"(bytes) : "memory");
}
__device__ __forceinline__ void mbar_arrive(uint32_t a) {
    asm volatile("mbarrier.arrive.shared.b64 _, [%0];" :: "r"(a) : "memory");
}
__device__ __forceinline__ void mbar_wait(uint32_t a, uint32_t ph) {
    asm volatile(
        "{\n\t.reg .pred P;\n"
        "W1_%=:\n\t"
        "mbarrier.try_wait.parity.acquire.cta.shared::cta.b64 P, [%0], %1, 0x989680;\n\t"
        "@P bra W2_%=;\n\t"
        "bra W1_%=;\n"
        "W2_%=:\n\t}"
        :: "r"(a), "r"(ph) : "memory");
}
__device__ __forceinline__ void bulk1d(uint32_t dst, const void* src,
                                       uint32_t bytes, uint32_t mbar) {
    asm volatile(
        "cp.async.bulk.shared::cta.global.mbarrier::complete_tx::bytes "
        "[%0], [%1], %2, [%3];"
        :: "r"(dst), "l"(src), "r"(bytes), "r"(mbar) : "memory");
}

// ---------------------------------------------------------------------------
// Kernel 1: analytic upsample-mean score, bulk-async fed.
// One CTA per plane; 64KB plane staged as 4x16KB chunks (depth-4).
// ---------------------------------------------------------------------------
__global__ void __launch_bounds__(256) scores_kernel(const float* __restrict__ readout) {
    extern __shared__ __align__(1024) char sdyn[];
    __shared__ float wA[HR];
    __shared__ float red[8];
    __shared__ __align__(8) unsigned long long mbar[4];

    const int tid = threadIdx.x;
    const int plane = blockIdx.x;

    uint32_t mb[4];
    #pragma unroll
    for (int i = 0; i < 4; i++) mb[i] = smem_u32(&mbar[i]);

    if (tid == 0) {
        #pragma unroll
        for (int i = 0; i < 4; i++) mbar_init(mb[i], 1);
    }
    if (tid < HR) wA[tid] = 0.0f;
    __syncthreads();

    if (tid == 0) {
        const char* src = (const char*)(readout + (size_t)plane * (HR * WR));
        #pragma unroll
        for (int ch = 0; ch < 4; ch++) {
            mbar_expect(mb[ch], 16384);
            bulk1d(smem_u32(sdyn + ch * 16384), src + ch * 16384, 16384, mb[ch]);
        }
    }

    {
        const float cst = (float)(127.0 / 255.0);
        float pos = (float)tid * cst;
        int i0 = (int)pos;
        if (i0 > HR - 2) i0 = HR - 2;
        float w = pos - (float)i0;
        atomicAdd(&wA[i0], 1.0f - w);
        atomicAdd(&wA[i0 + 1], w);
    }
    __syncthreads();

    float acc0 = 0.f, acc1 = 0.f, acc2 = 0.f, acc3 = 0.f;
    #pragma unroll
    for (int ch = 0; ch < 4; ch++) {
        mbar_wait(mb[ch], 0);
        const float4* __restrict__ d = (const float4*)(sdyn + ch * 16384);
        #pragma unroll
        for (int j = 0; j < 4; j++) {
            int f4 = tid + j * 256;                 // within chunk
            float4 v = d[f4];
            int base = ((ch << 10) + f4) << 2;
            int row = base >> 7;
            int col = base & 127;
            float wr = wA[row];
            float s = wA[col] * v.x + wA[col + 1] * v.y +
                      wA[col + 2] * v.z + wA[col + 3] * v.w;
            if (j == 0) acc0 += wr * s;
            else if (j == 1) acc1 += wr * s;
            else if (j == 2) acc2 += wr * s;
            else acc3 += wr * s;
        }
    }

    float acc = (acc0 + acc1) + (acc2 + acc3);
    #pragma unroll
    for (int s = 16; s > 0; s >>= 1)
        acc += __shfl_down_sync(0xffffffffu, acc, s);
    if ((tid & 31) == 0) red[tid >> 5] = acc;
    __syncthreads();
    if (tid == 0) {
        float t = 0.f;
        #pragma unroll
        for (int w2 = 0; w2 < 8; w2++) t += red[w2];
        g_scores[plane] = t * (1.0f / (float)(Hc * Wc));
    }
}

// ---------------------------------------------------------------------------
// Kernel 2: per-batch descending bitonic sort (tie: lower index first).
// ---------------------------------------------------------------------------
__global__ void topk_kernel() {
    __shared__ float sv[CR];
    __shared__ int   si[CR];
    const int tid = threadIdx.x;
    const int b = blockIdx.x;

    sv[tid] = g_scores[b * CR + tid];
    si[tid] = tid;
    __syncthreads();

    for (int k = 2; k <= CR; k <<= 1) {
        for (int j = k >> 1; j > 0; j >>= 1) {
            int ixj = tid ^ j;
            if (ixj > tid) {
                float va = sv[tid], vb = sv[ixj];
                int   ia = si[tid], ib = si[ixj];
                bool first = (va > vb) || (va == vb && ia < ib);
                bool ascSeg = ((tid & k) == 0);
                bool doSwap = ascSeg ? (!first) : first;
                if (doSwap) {
                    sv[tid] = vb; sv[ixj] = va;
                    si[tid] = ib; si[ixj] = ia;
                }
            }
            __syncthreads();
        }
    }
    if (tid < C) g_idx[b * C + tid] = si[tid];
}

// ---------------------------------------------------------------------------
// Kernel 3: bulk-async ring-pipelined fused upsample + gated blend.
// Block = (plane, half): 8 tiles of 16 rows x 256 cols. 288 threads:
// warps 0-7 consume, thread 256 produces. 3-stage ring, full/empty mbarriers.
// Stage = 16KB x-tile + 10-row readout window (5KB), both contiguous in gmem.
// ---------------------------------------------------------------------------
#define NSTAGE   3
#define X_BYTES  16384
#define R_ROWS   10
#define R_BYTES  (R_ROWS * WR * 4)
#define STAGE_SZ (X_BYTES + R_BYTES)          // 21504, multiple of 1024
#define TX_BYTES (X_BYTES + R_BYTES)
#define NTILES   8

__global__ void __launch_bounds__(288) fuse_kernel(
    const float* __restrict__ x,
    const float* __restrict__ readout,
    const float* __restrict__ weight,
    const float* __restrict__ bias,
    float* __restrict__ out)
{
    extern __shared__ __align__(1024) char sm[];
    __shared__ __align__(8) unsigned long long fbar[NSTAGE];
    __shared__ __align__(8) unsigned long long ebar[NSTAGE];

    const int tid = threadIdx.x;
    const int bx = blockIdx.x;
    const int plane = bx >> 1;
    const int half  = bx & 1;
    const int b = plane >> 6;
    const int c = plane & (C - 1);
    const int ch = g_idx[plane];
    const int ybase = half * 128;

    uint32_t fmb[NSTAGE], emb[NSTAGE];
    #pragma unroll
    for (int s = 0; s < NSTAGE; s++) {
        fmb[s] = smem_u32(&fbar[s]);
        emb[s] = smem_u32(&ebar[s]);
    }

    if (tid == 0) {
        #pragma unroll
        for (int s = 0; s < NSTAGE; s++) {
            mbar_init(fmb[s], 1);
            mbar_init(emb[s], 256);
        }
    }
    __syncthreads();

    if (tid == 256) {
        // producer
        const char* xsrc =
            (const char*)(x + ((size_t)plane * Hc + ybase) * Wc);
        const char* rsrc =
            (const char*)(readout + ((size_t)b * CR + ch) * (HR * WR));
        for (int t = 0; t < NTILES; t++) {
            int s = t % NSTAGE;
            int k = t / NSTAGE;
            if (t >= NSTAGE) mbar_wait(emb[s], (k - 1) & 1);
            int y0 = ybase + t * 16;
            int iy_lo = (y0 * 127) / 255;
            int iy_start = iy_lo > HR - R_ROWS ? HR - R_ROWS : iy_lo;
            uint32_t st = smem_u32(sm + s * STAGE_SZ);
            mbar_expect(fmb[s], TX_BYTES);
            bulk1d(st,           xsrc + (size_t)t * X_BYTES, X_BYTES, fmb[s]);
            bulk1d(st + X_BYTES, rsrc + (size_t)iy_start * WR * 4, R_BYTES, fmb[s]);
        }
    } else if (tid < 256) {
        // consumers
        const float w0 = __ldg(weight + 2 * c);
        const float w1 = __ldg(weight + 2 * c + 1);
        const float bs = __ldg(bias + c);
        const float cst = (float)(127.0 / 255.0);

        const int r   = tid >> 4;       // 0..15 row in tile
        const int sl0 = tid & 15;

        for (int t = 0; t < NTILES; t++) {
            const int s = t % NSTAGE;
            const int k = t / NSTAGE;
            mbar_wait(fmb[s], k & 1);

            const float* __restrict__ xs = (const float*)(sm + s * STAGE_SZ);
            const float* __restrict__ rs =
                (const float*)(sm + s * STAGE_SZ + X_BYTES);

            const int y0 = ybase + t * 16;
            const int iy_lo = (y0 * 127) / 255;
            const int iy_start = iy_lo > HR - R_ROWS ? HR - R_ROWS : iy_lo;
            const int y = y0 + r;

            float posy = (float)y * cst;
            int iy0 = (int)posy;
            if (iy0 > HR - 2) iy0 = HR - 2;
            const float wy  = posy - (float)iy0;
            const float wy0 = 1.0f - wy;

            const float* __restrict__ s0 = rs + (iy0 - iy_start) * WR;
            const float* __restrict__ s1 = s0 + WR;

            const size_t obase = ((size_t)plane * Hc + y) * Wc;

            #pragma unroll
            for (int q = 0; q < 4; q++) {
                const int slot = sl0 + 16 * q;
                const int x0 = slot << 2;
                float4 xq = ((const float4*)xs)[r * 64 + slot];
                float xv[4] = {xq.x, xq.y, xq.z, xq.w};
                float os[4];
                #pragma unroll
                for (int j = 0; j < 4; j++) {
                    float posx = (float)(x0 + j) * cst;
                    int ix0 = (int)posx;
                    if (ix0 > WR - 2) ix0 = WR - 2;
                    float wx = posx - (float)ix0;
                    // reference order: H first, then W
                    float a  = s0[ix0]     * wy0 + s1[ix0]     * wy;
                    float bb = s0[ix0 + 1] * wy0 + s1[ix0 + 1] * wy;
                    float rv = a * (1.0f - wx) + bb * wx;
                    float tt = xv[j] * w0 + rv * w1 + bs;
                    float gate = 1.0f / (1.0f + __expf(-tt));
                    os[j] = xv[j] + gate * (rv - xv[j]);
                }
                __stcs((float4*)(out + obase + x0),
                       make_float4(os[0], os[1], os[2], os[3]));
            }
            mbar_arrive(emb[s]);
        }
    }
}

// ---------------------------------------------------------------------------
extern "C" void kernel_launch(void* const* d_in, const int* in_sizes, int n_in,
                              void* d_out, int out_size)
{
    const float* x       = (const float*)d_in[0];
    const float* readout = (const float*)d_in[1];
    const float* weight  = (const float*)d_in[2];
    const float* bias    = (const float*)d_in[3];
    float* out = (float*)d_out;

    cudaFuncSetAttribute(scores_kernel,
                         cudaFuncAttributeMaxDynamicSharedMemorySize, 65536);
    cudaFuncSetAttribute(fuse_kernel,
                         cudaFuncAttributeMaxDynamicSharedMemorySize,
                         NSTAGE * STAGE_SZ);

    scores_kernel<<<B * CR, 256, 65536>>>(readout);
    topk_kernel<<<B, CR>>>();
    fuse_kernel<<<B * C * 2, 288, NSTAGE * STAGE_SZ>>>(x, readout, weight, bias, out);
}

// round 9
// speedup vs baseline: 1.1685x; 1.1685x over previous
#include <cuda_runtime.h>
#include <math.h>
#include <stdint.h>

#define B  8
#define C  64
#define Hc 256
#define Wc 256
#define CR 128
#define HR 128
#define WR 128

__device__ float g_scores[B * CR];
__device__ int   g_idx[B * C];

// ---------------------------------------------------------------------------
// Kernel 1: analytic upsample-mean score (proven R4 version, ~14us).
// ---------------------------------------------------------------------------
__global__ void __launch_bounds__(256) scores_kernel(const float* __restrict__ readout) {
    __shared__ float wA[HR];
    __shared__ float red[8];
    const int tid = threadIdx.x;

    if (tid < HR) wA[tid] = 0.0f;
    __syncthreads();
    {
        const float cst = (float)(127.0 / 255.0);
        float pos = (float)tid * cst;
        int i0 = (int)pos;
        if (i0 > HR - 2) i0 = HR - 2;
        float w = pos - (float)i0;
        atomicAdd(&wA[i0], 1.0f - w);
        atomicAdd(&wA[i0 + 1], w);
    }
    __syncthreads();

    const int plane = blockIdx.x;
    const float4* __restrict__ src =
        (const float4*)(readout + (size_t)plane * (HR * WR));

    float acc0 = 0.f, acc1 = 0.f, acc2 = 0.f, acc3 = 0.f;
    #pragma unroll
    for (int half = 0; half < 2; half++) {
        float4 v[8];
        #pragma unroll
        for (int j = 0; j < 8; j++)
            v[j] = src[tid + (half * 8 + j) * 256];
        #pragma unroll
        for (int j = 0; j < 8; j++) {
            int base = (tid + (half * 8 + j) * 256) << 2;
            int row = base >> 7;
            int col = base & 127;
            float wr = wA[row];
            float s = wA[col] * v[j].x + wA[col + 1] * v[j].y +
                      wA[col + 2] * v[j].z + wA[col + 3] * v[j].w;
            if (j == 0 || j == 4) acc0 += wr * s;
            else if (j == 1 || j == 5) acc1 += wr * s;
            else if (j == 2 || j == 6) acc2 += wr * s;
            else acc3 += wr * s;
        }
    }

    float acc = (acc0 + acc1) + (acc2 + acc3);
    #pragma unroll
    for (int s = 16; s > 0; s >>= 1)
        acc += __shfl_down_sync(0xffffffffu, acc, s);
    if ((tid & 31) == 0) red[tid >> 5] = acc;
    __syncthreads();
    if (tid == 0) {
        float t = 0.f;
        #pragma unroll
        for (int w2 = 0; w2 < 8; w2++) t += red[w2];
        g_scores[plane] = t * (1.0f / (float)(Hc * Wc));
    }
}

// ---------------------------------------------------------------------------
// Kernel 2: per-batch descending bitonic sort (tie: lower index first).
// ---------------------------------------------------------------------------
__global__ void topk_kernel() {
    __shared__ float sv[CR];
    __shared__ int   si[CR];
    const int tid = threadIdx.x;
    const int b = blockIdx.x;

    sv[tid] = g_scores[b * CR + tid];
    si[tid] = tid;
    __syncthreads();

    for (int k = 2; k <= CR; k <<= 1) {
        for (int j = k >> 1; j > 0; j >>= 1) {
            int ixj = tid ^ j;
            if (ixj > tid) {
                float va = sv[tid], vb = sv[ixj];
                int   ia = si[tid], ib = si[ixj];
                bool first = (va > vb) || (va == vb && ia < ib);
                bool ascSeg = ((tid & k) == 0);
                bool doSwap = ascSeg ? (!first) : first;
                if (doSwap) {
                    sv[tid] = vb; sv[ixj] = va;
                    si[tid] = ib; si[ixj] = ia;
                }
            }
            __syncthreads();
        }
    }
    if (tid < C) g_idx[b * C + tid] = si[tid];
}

// ---------------------------------------------------------------------------
// Kernel 3: fused bilinear-upsample + gated blend.
// R4 load/compute structure; OUTPUT via TMA bulk store (smem -> gmem, one
// contiguous 16KB block per CTA) so stores leave the LSU/L1tex path.
// ---------------------------------------------------------------------------
__global__ void __launch_bounds__(256) fuse_kernel(
    const float* __restrict__ x,
    const float* __restrict__ readout,
    const float* __restrict__ weight,
    const float* __restrict__ bias,
    float* __restrict__ out)
{
    __shared__ __align__(1024) float ostage[16 * 256];   // 16KB
    __shared__ float srow[10 * WR];

    const int plane = blockIdx.z;
    const int b = plane >> 6;
    const int c = plane & (C - 1);
    const int ch = g_idx[plane];

    const float* __restrict__ rsrc =
        readout + ((size_t)b * CR + ch) * (HR * WR);

    const int y0 = blockIdx.y << 4;          // 16 rows per block
    const float cst = (float)(127.0 / 255.0);

    int iy_lo = (int)((float)y0 * cst);        if (iy_lo > HR - 2) iy_lo = HR - 2;
    int iy_hi = (int)((float)(y0 + 15) * cst); if (iy_hi > HR - 2) iy_hi = HR - 2;
    iy_hi += 1;
    const int nrows = iy_hi - iy_lo + 1;      // <= 10

    const int tid = threadIdx.x;

    // ---- front-batched stage loads (up to 320 slots over 256 threads) ----
    const int nslots = nrows * 32;
    float4 sv0, sv1;
    const bool st0 = (tid < nslots);
    const bool st1 = (tid + 256 < nslots);
    if (st0)
        sv0 = __ldg((const float4*)(rsrc + (iy_lo + (tid >> 5)) * WR + ((tid & 31) << 2)));
    if (st1)
        sv1 = __ldg((const float4*)(rsrc + (iy_lo + ((tid + 256) >> 5)) * WR + (((tid + 256) & 31) << 2)));

    // ---- front-batched x loads: 4 rows, dense float4 lanes ----
    const int tx = tid & 63;
    const int ty = tid >> 6;                  // 0..3
    const int x0 = tx << 2;

    float4 xv[4];
    #pragma unroll
    for (int r = 0; r < 4; r++) {
        int y = y0 + ty + (r << 2);
        xv[r] = __ldcs((const float4*)(x + ((size_t)plane * Hc + y) * Wc + x0));
    }

    if (st0) *(float4*)(srow + (tid >> 5) * WR + ((tid & 31) << 2)) = sv0;
    if (st1) *(float4*)(srow + ((tid + 256) >> 5) * WR + (((tid + 256) & 31) << 2)) = sv1;
    __syncthreads();

    const float w0 = __ldg(weight + 2 * c);
    const float w1 = __ldg(weight + 2 * c + 1);
    const float bs = __ldg(bias + c);

    int   ixA[4];
    float wxA[4];
    #pragma unroll
    for (int k = 0; k < 4; k++) {
        float posx = (float)(x0 + k) * cst;
        int ix0 = (int)posx;
        if (ix0 > WR - 2) ix0 = WR - 2;
        ixA[k] = ix0;
        wxA[k] = posx - (float)ix0;
    }

    #pragma unroll
    for (int r = 0; r < 4; r++) {
        const int yy = ty + (r << 2);         // row within tile
        const int y = y0 + yy;
        float posy = (float)y * cst;
        int iy0 = (int)posy;
        if (iy0 > HR - 2) iy0 = HR - 2;
        const float wy = posy - (float)iy0;
        const float wy0 = 1.0f - wy;

        const float* __restrict__ s0 = srow + (iy0 - iy_lo) * WR;
        const float* __restrict__ s1 = s0 + WR;

        float xs[4] = {xv[r].x, xv[r].y, xv[r].z, xv[r].w};
        float os[4];
        #pragma unroll
        for (int k = 0; k < 4; k++) {
            int ix0 = ixA[k];
            // reference order: interpolate along H first, then W
            float a  = s0[ix0]     * wy0 + s1[ix0]     * wy;
            float bb = s0[ix0 + 1] * wy0 + s1[ix0 + 1] * wy;
            float rv = a * (1.0f - wxA[k]) + bb * wxA[k];
            float t = xs[k] * w0 + rv * w1 + bs;
            float gate = 1.0f / (1.0f + __expf(-t));
            os[k] = xs[k] + gate * (rv - xs[k]);
        }
        *(float4*)(ostage + yy * 256 + x0) = make_float4(os[0], os[1], os[2], os[3]);
    }

    __syncthreads();

    if (tid == 0) {
        asm volatile("fence.proxy.async.shared::cta;" ::: "memory");
        uint32_t saddr;
        asm("{ .reg .u64 t; cvta.to.shared.u64 t, %1; cvt.u32.u64 %0, t; }"
            : "=r"(saddr) : "l"(ostage));
        const float* gdst = out + ((size_t)plane * Hc + y0) * Wc;
        asm volatile(
            "cp.async.bulk.global.shared::cta.bulk_group [%0], [%1], %2;"
            :: "l"(gdst), "r"(saddr), "r"(16384) : "memory");
        asm volatile("cp.async.bulk.commit_group;" ::: "memory");
        asm volatile("cp.async.bulk.wait_group 0;" ::: "memory");
    }
}

// ---------------------------------------------------------------------------
extern "C" void kernel_launch(void* const* d_in, const int* in_sizes, int n_in,
                              void* d_out, int out_size)
{
    const float* x       = (const float*)d_in[0];
    const float* readout = (const float*)d_in[1];
    const float* weight  = (const float*)d_in[2];
    const float* bias    = (const float*)d_in[3];
    float* out = (float*)d_out;

    scores_kernel<<<B * CR, 256>>>(readout);
    topk_kernel<<<B, CR>>>();

    dim3 blk(256, 1, 1);
    dim3 grd(1, Hc / 16, B * C);   // 8192 blocks
    fuse_kernel<<<grd, blk>>>(x, readout, weight, bias, out);
}